// round 1
// baseline (speedup 1.0000x reference)
#include <cuda_runtime.h>
#include <cstdint>

#define N_NODES 100000
#define N_EDGES 800000
#define DIM 64
#define HEADS 4
#define NCHUNK 98   // ceil(N_NODES/1024)

// ---------------- scratch (static __device__, no allocations) ----------------
__device__ float g_q[N_NODES * DIM];
__device__ float g_k[N_NODES * DIM];
__device__ float g_v[N_NODES * DIM];
__device__ float g_p[N_NODES * DIM * HEADS];     // [n][h][64]
__device__ float g_logits[N_EDGES * HEADS];      // logits, then exp(logit-m)
__device__ float g_csr_att[N_EDGES * HEADS];     // normalized att in CSR order
__device__ int   g_src[N_EDGES];
__device__ int   g_dst[N_EDGES];
__device__ int   g_pos[N_EDGES];                 // edge -> CSR slot
__device__ int   g_csr_src[N_EDGES];
__device__ int   g_deg[N_NODES];
__device__ int   g_rowptr[N_NODES + 1];
__device__ int   g_cursor[N_NODES];
__device__ int   g_chunksum[NCHUNK];
__device__ int   g_chunkoff[NCHUNK];
__device__ unsigned g_menc[N_NODES * HEADS];
__device__ float g_denom[N_NODES * HEADS];
__device__ float g_zA[N_NODES * DIM];
__device__ float g_zB[N_NODES * DIM];
__device__ int   g_is64;

// ordered-uint encoding of float for atomicMax
__device__ __forceinline__ unsigned fenc(float f) {
    unsigned u = __float_as_uint(f);
    return (u & 0x80000000u) ? ~u : (u | 0x80000000u);
}
__device__ __forceinline__ float fdec(unsigned u) {
    unsigned b = (u & 0x80000000u) ? (u & 0x7FFFFFFFu) : ~u;
    return __uint_as_float(b);
}

// ---------------- kernels ----------------

// detect whether edge_index is really int64 or silently int32 (JAX x64 off)
__global__ void k_detect(const long long* __restrict__ ei) {
    int ok = 1;
    for (int i = 0; i < 64; i++) {
        long long v = ei[i];
        if (v < 0 || v >= N_NODES) ok = 0;
    }
    g_is64 = ok;
}

__global__ void k_zero() {
    int i = blockIdx.x * blockDim.x + threadIdx.x;
    if (i < N_NODES * HEADS) { g_menc[i] = 0u; g_denom[i] = 0.0f; }
    if (i < N_NODES) g_deg[i] = 0;
}

__global__ void k_prep(const long long* __restrict__ ei) {
    int i = blockIdx.x * blockDim.x + threadIdx.x;
    if (i >= N_EDGES) return;
    int s, d;
    if (g_is64) {
        s = (int)ei[i];
        d = (int)ei[N_EDGES + i];
    } else {
        const int* e32 = (const int*)ei;
        s = e32[i];
        d = e32[N_EDGES + i];
    }
    g_src[i] = s;
    g_dst[i] = d;
    atomicAdd(&g_deg[d], 1);
}

__global__ void k_chunksum() {
    __shared__ int sh[256];
    int b = blockIdx.x, t = threadIdx.x;
    int base = b * 1024;
    int sum = 0;
    for (int k = 0; k < 4; k++) {
        int i = base + k * 256 + t;
        if (i < N_NODES) sum += g_deg[i];
    }
    sh[t] = sum;
    __syncthreads();
    for (int off = 128; off; off >>= 1) {
        if (t < off) sh[t] += sh[t + off];
        __syncthreads();
    }
    if (t == 0) g_chunksum[b] = sh[0];
}

__global__ void k_scanmid() {
    int run = 0;
    for (int c = 0; c < NCHUNK; c++) {
        g_chunkoff[c] = run;
        run += g_chunksum[c];
    }
    g_rowptr[N_NODES] = run;
}

__global__ void k_scanchunk() {
    __shared__ int s[1024];
    int b = blockIdx.x, t = threadIdx.x;
    int i = b * 1024 + t;
    int v = (i < N_NODES) ? g_deg[i] : 0;
    s[t] = v;
    __syncthreads();
    for (int off = 1; off < 1024; off <<= 1) {
        int add = (t >= off) ? s[t - off] : 0;
        __syncthreads();
        s[t] += add;
        __syncthreads();
    }
    if (i < N_NODES) {
        int ex = g_chunkoff[b] + s[t] - v;   // exclusive prefix
        g_rowptr[i] = ex;
        g_cursor[i] = ex;
    }
}

// q/k/v projections: 32 rows per block, register-blocked (8 rows/thread-group)
__global__ void k_qkv(const float* __restrict__ x, const float* __restrict__ Wq,
                      const float* __restrict__ Wk, const float* __restrict__ Wv) {
    __shared__ float xs[32][64];
    int n0 = blockIdx.x * 32;
    int t = threadIdx.x;
    for (int k = 0; k < 8; k++) {
        int L = k * 256 + t;
        xs[L >> 6][L & 63] = x[n0 * 64 + L];
    }
    __syncthreads();
    int col = t & 63, rg = t >> 6;
    float aq[8] = {0}, ak[8] = {0}, av[8] = {0};
#pragma unroll 4
    for (int j = 0; j < 64; j++) {
        float wq = Wq[j * 64 + col];
        float wk = Wk[j * 64 + col];
        float wv = Wv[j * 64 + col];
#pragma unroll
        for (int r = 0; r < 8; r++) {
            float xv = xs[rg * 8 + r][j];
            aq[r] += xv * wq;
            ak[r] += xv * wk;
            av[r] += xv * wv;
        }
    }
#pragma unroll
    for (int r = 0; r < 8; r++) {
        int n = n0 + rg * 8 + r;
        g_q[n * 64 + col] = aq[r];
        g_k[n * 64 + col] = ak[r];
        g_v[n * 64 + col] = av[r];
    }
}

// p[n,h,j] = sum_d We[j, h*16+d] * q[n, h*16+d]   (16 nodes per block)
__global__ void k_p(const float* __restrict__ We) {
    __shared__ float qs[16][64];
    int n0 = blockIdx.x * 16, t = threadIdx.x;
    for (int k = 0; k < 4; k++) {
        int L = k * 256 + t;
        qs[L >> 6][L & 63] = g_q[n0 * 64 + L];
    }
    __syncthreads();
    int h = t >> 6, j = t & 63;
    const float4* wp = (const float4*)(We + j * 64 + h * 16);
    float4 w0 = wp[0], w1 = wp[1], w2 = wp[2], w3 = wp[3];
#pragma unroll 4
    for (int nl = 0; nl < 16; nl++) {
        const float* qr = &qs[nl][h * 16];
        float acc = w0.x * qr[0] + w0.y * qr[1] + w0.z * qr[2] + w0.w * qr[3]
                  + w1.x * qr[4] + w1.y * qr[5] + w1.z * qr[6] + w1.w * qr[7]
                  + w2.x * qr[8] + w2.y * qr[9] + w2.z * qr[10] + w2.w * qr[11]
                  + w3.x * qr[12] + w3.y * qr[13] + w3.z * qr[14] + w3.w * qr[15];
        g_p[(n0 + nl) * 256 + h * 64 + j] = acc;
    }
}

// logits: 64 edges/block, thread = (edge_local, head)
__global__ void k_logits(const float* __restrict__ ea) {
    __shared__ float eas[64 * 65];
    __shared__ int ss[64], sd[64];
    int e0 = blockIdx.x * 64, t = threadIdx.x;
    for (int k = 0; k < 16; k++) {
        int L = k * 256 + t;
        eas[(L >> 6) * 65 + (L & 63)] = ea[e0 * 64 + L];
    }
    if (t < 64) ss[t] = g_src[e0 + t];
    else if (t < 128) sd[t - 64] = g_dst[e0 + t - 64];
    __syncthreads();
    int el = t >> 2, h = t & 3;
    int dst = sd[el], src = ss[el];
    const float4* qp = (const float4*)(g_q + dst * 64 + h * 16);
    const float4* kp = (const float4*)(g_k + src * 64 + h * 16);
    float acc = 0.0f;
#pragma unroll
    for (int c = 0; c < 4; c++) {
        float4 qv = qp[c], kv = kp[c];
        acc += qv.x * kv.x + qv.y * kv.y + qv.z * kv.z + qv.w * kv.w;
    }
    const float4* pp = (const float4*)(g_p + dst * 256 + h * 64);
    const float* er = &eas[el * 65];
#pragma unroll
    for (int j = 0; j < 16; j++) {
        float4 pv = pp[j];
        acc += er[4 * j] * pv.x + er[4 * j + 1] * pv.y
             + er[4 * j + 2] * pv.z + er[4 * j + 3] * pv.w;
    }
    float logit = acc * 0.25f;
    g_logits[e0 * 4 + t] = logit;
    atomicMax(&g_menc[dst * 4 + h], fenc(logit));
}

__global__ void k_exp() {
    int i = blockIdx.x * blockDim.x + threadIdx.x;
    if (i >= N_EDGES * HEADS) return;
    int e = i >> 2, h = i & 3;
    int dst = g_dst[e];
    float m = fdec(g_menc[dst * 4 + h]);
    float ex = __expf(g_logits[i] - m);
    g_logits[i] = ex;
    atomicAdd(&g_denom[dst * 4 + h], ex);
}

__global__ void k_scatter() {
    int e = blockIdx.x * blockDim.x + threadIdx.x;
    if (e >= N_EDGES) return;
    int dst = g_dst[e];
    int p = atomicAdd(&g_cursor[dst], 1);
    g_pos[e] = p;
    g_csr_src[p] = g_src[e];
}

__global__ void k_norm() {
    int i = blockIdx.x * blockDim.x + threadIdx.x;
    if (i >= N_EDGES * HEADS) return;
    int e = i >> 2, h = i & 3;
    int dst = g_dst[e];
    float a = g_logits[i] / (g_denom[dst * 4 + h] + 1e-16f);
    g_csr_att[g_pos[e] * 4 + h] = a;
}

// propagation: warp per node, pure gather (no atomics)
__global__ void k_prop(int iter) {
    int gid = blockIdx.x * blockDim.x + threadIdx.x;
    int node = gid >> 5;
    if (node >= N_NODES) return;
    int lane = gid & 31;
    const float* zold = (iter == 0) ? g_v : ((iter & 1) ? g_zA : g_zB);
    float* znew = (iter & 1) ? g_zB : g_zA;
    int beg = g_rowptr[node], end = g_rowptr[node + 1];
    int h = lane >> 3;
    float ax = 0.0f, ay = 0.0f;
    for (int i = beg; i < end; i++) {
        int s = g_csr_src[i];
        float a = g_csr_att[i * 4 + h];
        float2 z = *(const float2*)(zold + s * 64 + lane * 2);
        ax += a * z.x;
        ay += a * z.y;
    }
    float2 vv = *(const float2*)(g_v + node * 64 + lane * 2);
    float2 o;
    o.x = 0.1f * vv.x + 0.9f * ax;
    o.y = 0.1f * vv.y + 0.9f * ay;
    *(float2*)(znew + node * 64 + lane * 2) = o;
}

__global__ void k_final(const float* __restrict__ x, float* __restrict__ out) {
    int i = blockIdx.x * blockDim.x + threadIdx.x;
    if (i < N_NODES * DIM) out[i] = x[i] + fmaxf(g_zB[i], 0.0f);
}

// ---------------- launch ----------------
extern "C" void kernel_launch(void* const* d_in, const int* in_sizes, int n_in,
                              void* d_out, int out_size) {
    const float*     x  = (const float*)d_in[0];
    const long long* ei = (const long long*)d_in[1];
    const float*     ea = (const float*)d_in[2];
    const float*     Wq = (const float*)d_in[3];
    const float*     Wk = (const float*)d_in[4];
    const float*     Wv = (const float*)d_in[5];
    const float*     We = (const float*)d_in[6];
    float* out = (float*)d_out;

    k_detect<<<1, 1>>>(ei);
    k_zero<<<(N_NODES * HEADS + 255) / 256, 256>>>();
    k_prep<<<(N_EDGES + 255) / 256, 256>>>(ei);
    k_chunksum<<<NCHUNK, 256>>>();
    k_scanmid<<<1, 1>>>();
    k_scanchunk<<<NCHUNK, 1024>>>();
    k_qkv<<<N_NODES / 32, 256>>>(x, Wq, Wk, Wv);
    k_p<<<N_NODES / 16, 256>>>(We);
    k_logits<<<N_EDGES / 64, 256>>>(ea);
    k_exp<<<(N_EDGES * HEADS + 255) / 256, 256>>>();
    k_scatter<<<(N_EDGES + 255) / 256, 256>>>();
    k_norm<<<(N_EDGES * HEADS + 255) / 256, 256>>>();
    for (int it = 0; it < 8; it++)
        k_prop<<<(N_NODES * 32 + 255) / 256, 256>>>(it);
    k_final<<<(N_NODES * DIM + 255) / 256, 256>>>(x, out);
}